// round 14
// baseline (speedup 1.0000x reference)
#include <cuda_runtime.h>
#include <cuda_bf16.h>
#include <math.h>
#include <stdint.h>

// ---------------- problem constants ----------------
#define BATCH 32
#define HH 64
#define WW 64
#define CH 192
#define LL (HH*WW)            // 4096
#define NHEAD 6
#define HD 32
#define WSZ 8
#define SHIFT 4
#define NTOK 64
#define NWIN 64
#define MROWS (BATCH*LL)      // 131072
#define CHID (4*CH)           // 768

// ---------------- scratch (device globals; no allocs allowed) ----------------
__device__ __nv_bfloat16 g_qkv [MROWS*3*CH];
__device__ __nv_bfloat16 g_attn[MROWS*CH];
__device__ float         g_x2  [MROWS*CH];
__device__ __nv_bfloat16 g_h1  [MROWS*CHID];
// bf16 weights (converted once per launch)
__device__ __nv_bfloat16 g_wq[3*CH*CH];
__device__ __nv_bfloat16 g_wp[CH*CH];
__device__ __nv_bfloat16 g_w1[CHID*CH];
__device__ __nv_bfloat16 g_w2[CH*CHID];

// roll(-4,-4)+window-partition map (self-inverse)
__device__ __forceinline__ int win_to_img_row(int r) {
    int b   = r >> 12;
    int rem = r & 4095;
    int win = rem >> 6;
    int n   = rem & 63;
    int hs  = ((win >> 3) << 3) + (n >> 3);
    int ws  = ((win & 7)  << 3) + (n & 7);
    int hh  = (hs + SHIFT) & 63;
    int ww  = (ws + SHIFT) & 63;
    return (b << 12) + (hh << 6) + ww;
}

// ---------------- asm helpers ----------------
__device__ __forceinline__ uint32_t smem_u32(const void* p) {
    uint32_t a;
    asm("{ .reg .u64 t; cvta.to.shared.u64 t, %1; cvt.u32.u64 %0, t; }" : "=r"(a) : "l"(p));
    return a;
}
__device__ __forceinline__ void cp16(uint32_t dst, const void* src) {
    asm volatile("cp.async.cg.shared.global [%0], [%1], 16;" :: "r"(dst), "l"(src));
}
#define CP_COMMIT() asm volatile("cp.async.commit_group;" ::: "memory")
#define CP_WAIT(n)  asm volatile("cp.async.wait_group %0;" :: "n"(n) : "memory")
#define LDSM4(r0, r1, r2, r3, a) \
    asm volatile("ldmatrix.sync.aligned.m8n8.x4.shared.b16 {%0,%1,%2,%3}, [%4];" \
                 : "=r"(r0), "=r"(r1), "=r"(r2), "=r"(r3) : "r"(a))
#define LDSM4T(r0, r1, r2, r3, a) \
    asm volatile("ldmatrix.sync.aligned.m8n8.x4.trans.shared.b16 {%0,%1,%2,%3}, [%4];" \
                 : "=r"(r0), "=r"(r1), "=r"(r2), "=r"(r3) : "r"(a))

__device__ __forceinline__ void mma_bf16(float* d, const unsigned* a, const unsigned* b) {
    asm volatile(
        "mma.sync.aligned.m16n8k16.row.col.f32.bf16.bf16.f32 "
        "{%0,%1,%2,%3}, {%4,%5,%6,%7}, {%8,%9}, {%0,%1,%2,%3};"
        : "+f"(d[0]), "+f"(d[1]), "+f"(d[2]), "+f"(d[3])
        : "r"(a[0]), "r"(a[1]), "r"(a[2]), "r"(a[3]), "r"(b[0]), "r"(b[1]));
}
__device__ __forceinline__ unsigned pack_bf16(float lo, float hi) {
    __nv_bfloat162 h = __floats2bfloat162_rn(lo, hi);
    return *(unsigned*)&h;
}
#define SWZ16(c, r) ((((c) & ~7) | (((c) & 7) ^ ((r) & 7))) << 4)

// ---------------- fused fp32 -> bf16 weight conversion ----------------
#define NWQ (3*CH*CH)
#define NWP (CH*CH)
#define NW1 (CHID*CH)
#define NW2 (CH*CHID)
__global__ void cvt_all(const float* __restrict__ wq, const float* __restrict__ wp,
                        const float* __restrict__ w1, const float* __restrict__ w2,
                        __nv_bfloat16* __restrict__ dq, __nv_bfloat16* __restrict__ dp,
                        __nv_bfloat16* __restrict__ d1, __nv_bfloat16* __restrict__ d2) {
    int i = (blockIdx.x * 256 + threadIdx.x) * 4;
    const float* s; __nv_bfloat16* d; int off;
    if (i < NWQ)                       { s = wq; d = dq; off = i; }
    else if (i < NWQ+NWP)              { s = wp; d = dp; off = i - NWQ; }
    else if (i < NWQ+NWP+NW1)          { s = w1; d = d1; off = i - NWQ - NWP; }
    else if (i < NWQ+NWP+NW1+NW2)      { s = w2; d = d2; off = i - NWQ - NWP - NW1; }
    else return;
    float4 v = *(const float4*)&s[off];
    *(__nv_bfloat162*)&d[off]   = __floats2bfloat162_rn(v.x, v.y);
    *(__nv_bfloat162*)&d[off+2] = __floats2bfloat162_rn(v.z, v.w);
}

// ---------------- full-K-resident GEMM (K=192), LN fused into A-builder ----------------
// BM=64, BN=96, 256 threads = 8 warps (4m x 2n), warp tile 16x48, 12 k-steps.
// Smem: A 64x384B swizzled (24KB) + B 96x384B swizzled (36KB) = 60KB, 3 CTAs/SM.
// MODE 0 (qkv): A = LN(x rows gathered via win_to_img_row); +bias, bf16 out
// MODE 1 (proj): A = attn bf16 rows; epilogue scatter + bias + resid, f32 out
// MODE 2 (fc1):  A = LN(x2 rows); gelu(acc+bias), bf16 out
#define FK_BOFF 24576
#define FK_TOT  (24576 + 36864)

template<int MODE>
__global__ __launch_bounds__(256, 3)
void gemm_fk(const void* __restrict__ AsrcV, const __nv_bfloat16* __restrict__ Bw,
             const float* __restrict__ bias,
             const float* __restrict__ lng, const float* __restrict__ lnb,
             const float* __restrict__ resid,
             void* __restrict__ CoutV, int Ncols) {
    extern __shared__ __align__(1024) unsigned char sm[];
    uint32_t sa = smem_u32(sm);
    uint32_t sbb = sa + FK_BOFF;

    int tid = threadIdx.x;
    int w = tid >> 5, lane = tid & 31;
    int rowBase = blockIdx.y * 64;
    int colBase = blockIdx.x * 96;

    // ---- B tile: 96 rows x 24 chunks of 16B ----
    #pragma unroll
    for (int i = 0; i < 9; i++) {
        int id = tid + i*256;
        int r = id / 24, c = id % 24;
        cp16(sbb + (uint32_t)(r*384 + SWZ16(c, r)), Bw + (size_t)(colBase + r)*CH + c*8);
    }

    // ---- A tile ----
    if (MODE == 1) {
        const __nv_bfloat16* A = (const __nv_bfloat16*)AsrcV;
        #pragma unroll
        for (int i = 0; i < 6; i++) {
            int id = tid + i*256;         // 64*24 = 1536
            int r = id / 24, c = id % 24;
            cp16(sa + (uint32_t)(r*384 + SWZ16(c, r)), A + (size_t)(rowBase + r)*CH + c*8);
        }
        CP_COMMIT();
    } else {
        CP_COMMIT();
        // LN: warp w handles rows 8w..8w+7; lane holds col pairs (2l, 2l+64i)
        const float* X = (const float*)AsrcV;
        float gg[6], bb[6];
        #pragma unroll
        for (int i = 0; i < 3; i++) {
            int col = 2*lane + 64*i;
            float2 gv = *(const float2*)&lng[col];
            float2 bv = *(const float2*)&lnb[col];
            gg[2*i] = gv.x; gg[2*i+1] = gv.y;
            bb[2*i] = bv.x; bb[2*i+1] = bv.y;
        }
        #pragma unroll
        for (int j = 0; j < 8; j++) {
            int r = w*8 + j;
            int gr = rowBase + r;
            int srcrow = (MODE == 0) ? win_to_img_row(gr) : gr;
            const float* xr = X + (size_t)srcrow * CH;
            float2 v[3];
            #pragma unroll
            for (int i = 0; i < 3; i++) v[i] = *(const float2*)&xr[2*lane + 64*i];
            float s = 0.f, s2 = 0.f;
            #pragma unroll
            for (int i = 0; i < 3; i++) {
                s  += v[i].x + v[i].y;
                s2 += v[i].x*v[i].x + v[i].y*v[i].y;
            }
            #pragma unroll
            for (int o = 16; o > 0; o >>= 1) {
                s  += __shfl_xor_sync(0xffffffffu, s,  o);
                s2 += __shfl_xor_sync(0xffffffffu, s2, o);
            }
            float mean = s * (1.0f/CH);
            float var  = s2 * (1.0f/CH) - mean*mean;
            float inv  = rsqrtf(var + 1e-5f);
            #pragma unroll
            for (int i = 0; i < 3; i++) {
                int col = 2*lane + 64*i;
                float f0 = (v[i].x - mean)*inv*gg[2*i]   + bb[2*i];
                float f1 = (v[i].y - mean)*inv*gg[2*i+1] + bb[2*i+1];
                unsigned pk = pack_bf16(f0, f1);
                int ch = col >> 3;
                uint32_t ad = sa + (uint32_t)(r*384 + SWZ16(ch, r) + ((col & 7) << 1));
                asm volatile("st.shared.b32 [%0], %1;" :: "r"(ad), "r"(pk));
            }
        }
    }
    CP_WAIT(0);
    __syncthreads();

    // ---- mma sweep: 12 k-steps, fully resident ----
    int wm = w >> 1, wn = w & 1;
    int mW = wm * 16, nW = wn * 48;
    int q  = lane >> 3, lrl = lane & 7;
    int qh = q >> 1, ql = q & 1;
    int aRow = mW + ql*8 + lrl;
    int bRow[3];
    #pragma unroll
    for (int p = 0; p < 3; p++) bRow[p] = nW + 8*(2*p + qh) + lrl;

    float acc[6][4];
    #pragma unroll
    for (int nt = 0; nt < 6; nt++)
        #pragma unroll
        for (int i = 0; i < 4; i++) acc[nt][i] = 0.f;

    #pragma unroll
    for (int kk = 0; kk < 12; kk++) {
        unsigned aF[4], bF[6][2];
        int cha = 2*kk + qh;
        LDSM4(aF[0], aF[1], aF[2], aF[3],
              sa + (uint32_t)(aRow*384 + SWZ16(cha, aRow)));
        int chb = 2*kk + ql;
        #pragma unroll
        for (int p = 0; p < 3; p++) {
            unsigned b0, b1, b2, b3;
            LDSM4(b0, b1, b2, b3,
                  sbb + (uint32_t)(bRow[p]*384 + SWZ16(chb, bRow[p])));
            bF[2*p][0] = b0; bF[2*p][1] = b1;
            bF[2*p+1][0] = b2; bF[2*p+1][1] = b3;
        }
        #pragma unroll
        for (int nt = 0; nt < 6; nt++)
            mma_bf16(acc[nt], aF, bF[nt]);
    }

    // ---- epilogue ----
    int g  = lane >> 2, tg = lane & 3;
    float*         CoutF = (float*)CoutV;
    __nv_bfloat16* CoutB = (__nv_bfloat16*)CoutV;
    #pragma unroll
    for (int half = 0; half < 2; half++) {
        int row = rowBase + mW + g + half*8;
        int dst = (MODE == 1) ? win_to_img_row(row) : row;
        #pragma unroll
        for (int nt = 0; nt < 6; nt++) {
            int col = colBase + nW + 8*nt + 2*tg;
            float2 bv = *(const float2*)&bias[col];
            float v0 = acc[nt][half*2 + 0] + bv.x;
            float v1 = acc[nt][half*2 + 1] + bv.y;
            if (MODE == 1) {
                float2 rr = *(const float2*)&resid[(size_t)dst*CH + col];
                float2 o; o.x = rr.x + v0; o.y = rr.y + v1;
                *(float2*)&CoutF[(size_t)dst*CH + col] = o;
            } else if (MODE == 2) {
                float o0 = 0.5f * v0 * (1.0f + erff(v0 * 0.70710678118654752f));
                float o1 = 0.5f * v1 * (1.0f + erff(v1 * 0.70710678118654752f));
                *(__nv_bfloat162*)&CoutB[(size_t)dst*Ncols + col] = __floats2bfloat162_rn(o0, o1);
            } else {
                *(__nv_bfloat162*)&CoutB[(size_t)dst*Ncols + col] = __floats2bfloat162_rn(v0, v1);
            }
        }
    }
}

// ---------------- pipelined GEMM for fc2 (K=768): 3-stage cp.async (R12) ----------------
#define STG   28672
#define BOFF  16384
#define GSM   (3*STG + 512)

template<int MODE>
__global__ __launch_bounds__(256, 2)
void gemm_lm(const __nv_bfloat16* __restrict__ A, const __nv_bfloat16* __restrict__ Bw,
             const float* __restrict__ bias, const float* __restrict__ resid,
             void* __restrict__ CoutV, int K, int Ncols) {
    extern __shared__ __align__(1024) unsigned char smem[];
    uint32_t sb = smem_u32(smem);

    int tid = threadIdx.x;
    int rowBase = blockIdx.y * 128;
    int colBase = blockIdx.x * 96;

    int lc = tid & 7;
    int lr0 = tid >> 3;
    const char* aPtr[4]; uint32_t aDst[4];
    #pragma unroll
    for (int i = 0; i < 4; i++) {
        int r = lr0 + 32*i;
        aPtr[i] = (const char*)(A + (size_t)(rowBase + r)*K + 8*lc);
        aDst[i] = (uint32_t)(r*128 + ((lc ^ (r & 7)) << 4));
    }
    const char* bPtr[3]; uint32_t bDst[3];
    #pragma unroll
    for (int i = 0; i < 3; i++) {
        int r = lr0 + 32*i;
        bPtr[i] = (const char*)(Bw + (size_t)(colBase + r)*K + 8*lc);
        bDst[i] = (uint32_t)(r*128 + ((lc ^ (r & 7)) << 4));
    }

    const int T = K >> 6;
    {
        #pragma unroll
        for (int i = 0; i < 4; i++) cp16(sb + aDst[i], aPtr[i]);
        #pragma unroll
        for (int i = 0; i < 3; i++) cp16(sb + BOFF + bDst[i], bPtr[i]);
        CP_COMMIT();
        #pragma unroll
        for (int i = 0; i < 4; i++) cp16(sb + STG + aDst[i], aPtr[i] + 128);
        #pragma unroll
        for (int i = 0; i < 3; i++) cp16(sb + STG + BOFF + bDst[i], bPtr[i] + 128);
        CP_COMMIT();
    }

    int w = tid >> 5, lane = tid & 31;
    int wm = w >> 1, wn = w & 1;
    int mW = wm * 32, nW = wn * 48;
    int q  = lane >> 3, lrl = lane & 7;
    int qh = q >> 1, ql = q & 1;

    int aRow[2];
    #pragma unroll
    for (int mt = 0; mt < 2; mt++) aRow[mt] = mW + 16*mt + ql*8 + lrl;
    int bRow[3];
    #pragma unroll
    for (int p = 0; p < 3; p++) bRow[p] = nW + 8*(2*p + qh) + lrl;

    float acc[2][6][4];
    #pragma unroll
    for (int mt = 0; mt < 2; mt++)
        #pragma unroll
        for (int nt = 0; nt < 6; nt++)
            #pragma unroll
            for (int i = 0; i < 4; i++) acc[mt][nt][i] = 0.f;

    int cBuf = 0, wBuf = 2;
    for (int t = 0; t < T; t++) {
        if (t + 1 < T) { CP_WAIT(1); } else { CP_WAIT(0); }
        __syncthreads();

        if (t + 2 < T) {
            int k0 = (t + 2) << 7;
            uint32_t dB = sb + (uint32_t)wBuf * STG;
            #pragma unroll
            for (int i = 0; i < 4; i++) cp16(dB + aDst[i], aPtr[i] + k0);
            #pragma unroll
            for (int i = 0; i < 3; i++) cp16(dB + BOFF + bDst[i], bPtr[i] + k0);
            CP_COMMIT();
        }

        uint32_t aB = sb + (uint32_t)cBuf * STG;
        uint32_t bB = aB + BOFF;

        #pragma unroll
        for (int kk = 0; kk < 4; kk++) {
            int ck = kk * 2;
            unsigned aF[2][4], bF[6][2];
            #pragma unroll
            for (int mt = 0; mt < 2; mt++) {
                int ch = ck + qh;
                uint32_t ad = aB + (uint32_t)(aRow[mt]*128 + (((ch ^ (aRow[mt] & 7)) << 4)));
                LDSM4(aF[mt][0], aF[mt][1], aF[mt][2], aF[mt][3], ad);
            }
            #pragma unroll
            for (int p = 0; p < 3; p++) {
                int ch = ck + ql;
                uint32_t bd = bB + (uint32_t)(bRow[p]*128 + (((ch ^ (bRow[p] & 7)) << 4)));
                LDSM4(bF[2*p][0], bF[2*p][1], bF[2*p+1][0], bF[2*p+1][1], bd);
            }
            #pragma unroll
            for (int mt = 0; mt < 2; mt++)
                #pragma unroll
                for (int nt = 0; nt < 6; nt++)
                    mma_bf16(acc[mt][nt], aF[mt], bF[nt]);
        }

        cBuf = (cBuf == 2) ? 0 : cBuf + 1;
        wBuf = (wBuf == 2) ? 0 : wBuf + 1;
    }

    int g  = lane >> 2, tg = lane & 3;
    float* CoutF = (float*)CoutV;
    #pragma unroll
    for (int mt = 0; mt < 2; mt++) {
        #pragma unroll
        for (int half = 0; half < 2; half++) {
            int row = rowBase + mW + 16*mt + g + half*8;
            #pragma unroll
            for (int nt = 0; nt < 6; nt++) {
                int col = colBase + nW + 8*nt + 2*tg;
                float2 bb = *(const float2*)&bias[col];
                float v0 = acc[mt][nt][half*2 + 0] + bb.x;
                float v1 = acc[mt][nt][half*2 + 1] + bb.y;
                float2 rr = *(const float2*)&resid[(size_t)row*Ncols + col];
                float2 o; o.x = rr.x + v0; o.y = rr.y + v1;
                *(float2*)&CoutF[(size_t)row*Ncols + col] = o;
            }
        }
    }
}

// ---------------- tensor-core attention (R12 winner) ----------------
__device__ __forceinline__ int region_of(int p) {
    return (p < 56) ? 0 : ((p < 60) ? 1 : 2);
}
#define ASM_RPB  73728
#define ASM_REG  (73728 + 5400)
#define ASM_TOT  (73728 + 5400 + 256)

__global__ __launch_bounds__(256)
void attn_mma(const __nv_bfloat16* __restrict__ qkv, const float* __restrict__ rpb,
              __nv_bfloat16* __restrict__ out) {
    extern __shared__ __align__(1024) unsigned char sm[];
    uint32_t sb = smem_u32(sm);
    float* rpbs = (float*)(sm + ASM_RPB);
    int*   regl = (int*)(sm + ASM_REG);

    int tid = threadIdx.x;
    int win = blockIdx.x;
    int rowbase = win * 64;

    #pragma unroll
    for (int i = 0; i < 18; i++) {
        int id = tid + i*256;
        int r = id / 72, c = id % 72;
        uint32_t dst = sb + (uint32_t)(r*1152 + SWZ16(c, r));
        cp16(dst, qkv + (size_t)(rowbase + r)*576 + c*8);
    }
    CP_COMMIT();
    for (int i = tid; i < 225*NHEAD; i += 256) {
        int idx = i / NHEAD, h = i % NHEAD;
        rpbs[h*225 + idx] = rpb[i];
    }
    if (tid < 64) {
        int wr = (win & 63) >> 3, wc = win & 7;
        regl[tid] = region_of(wr*8 + (tid >> 3))*3 + region_of(wc*8 + (tid & 7));
    }
    CP_WAIT(0);
    __syncthreads();

    int w = tid >> 5, lane = tid & 31;
    int q  = lane >> 3, lrl = lane & 7;
    int qh = q >> 1,   ql  = q & 1;
    int g  = lane >> 2, tg = lane & 3;

    for (int task = w; task < 24; task += 8) {
        int h = task >> 2, mt = task & 3;

        float sF[8][4];
        #pragma unroll
        for (int nt = 0; nt < 8; nt++)
            #pragma unroll
            for (int i = 0; i < 4; i++) sF[nt][i] = 0.f;

        #pragma unroll
        for (int kk = 0; kk < 2; kk++) {
            unsigned aF[4];
            {
                int r = mt*16 + ql*8 + lrl;
                int c = 4*h + 2*kk + qh;
                LDSM4(aF[0], aF[1], aF[2], aF[3], sb + (uint32_t)(r*1152 + SWZ16(c, r)));
            }
            #pragma unroll
            for (int p = 0; p < 4; p++) {
                unsigned b0, b1, b2, b3;
                int r = 16*p + qh*8 + lrl;
                int c = 24 + 4*h + 2*kk + ql;
                LDSM4(b0, b1, b2, b3, sb + (uint32_t)(r*1152 + SWZ16(c, r)));
                unsigned bb0[2] = {b0, b1}, bb1[2] = {b2, b3};
                mma_bf16(sF[2*p],   aF, bb0);
                mma_bf16(sF[2*p+1], aF, bb1);
            }
        }

        int n0 = mt*16 + g, n1 = n0 + 8;
        int r0g = regl[n0], r1g = regl[n1];
        int in0 = n0 >> 3, jn0 = n0 & 7;
        int in1 = n1 >> 3, jn1 = n1 & 7;
        const float* rh = rpbs + h*225;
        int jb0 = jn0 + 7 - 2*tg;
        int jb1 = jn1 + 7 - 2*tg;
        const float scale = 0.17677669529663687f;
        float mx0 = -1e30f, mx1 = -1e30f;
        #pragma unroll
        for (int nt = 0; nt < 8; nt++) {
            const float* r0p = rh + (in0 - nt + 7)*15 + jb0;
            const float* r1p = rh + (in1 - nt + 7)*15 + jb1;
            #pragma unroll
            for (int e = 0; e < 2; e++) {
                int col = nt*8 + 2*tg + e;
                int rm = regl[col];
                float v0 = sF[nt][e]   * scale + r0p[-e] + ((r0g == rm) ? 0.f : -100.f);
                float v1 = sF[nt][2+e] * scale + r1p[-e] + ((r1g == rm) ? 0.f : -100.f);
                sF[nt][e] = v0; sF[nt][2+e] = v1;
                mx0 = fmaxf(mx0, v0); mx1 = fmaxf(mx1, v1);
            }
        }
        mx0 = fmaxf(mx0, __shfl_xor_sync(0xffffffffu, mx0, 1));
        mx0 = fmaxf(mx0, __shfl_xor_sync(0xffffffffu, mx0, 2));
        mx1 = fmaxf(mx1, __shfl_xor_sync(0xffffffffu, mx1, 1));
        mx1 = fmaxf(mx1, __shfl_xor_sync(0xffffffffu, mx1, 2));
        float s0 = 0.f, s1 = 0.f;
        #pragma unroll
        for (int nt = 0; nt < 8; nt++) {
            #pragma unroll
            for (int e = 0; e < 2; e++) {
                float e0 = __expf(sF[nt][e]   - mx0);
                float e1 = __expf(sF[nt][2+e] - mx1);
                sF[nt][e] = e0;   s0 += e0;
                sF[nt][2+e] = e1; s1 += e1;
            }
        }
        s0 += __shfl_xor_sync(0xffffffffu, s0, 1);
        s0 += __shfl_xor_sync(0xffffffffu, s0, 2);
        s1 += __shfl_xor_sync(0xffffffffu, s1, 1);
        s1 += __shfl_xor_sync(0xffffffffu, s1, 2);

        float oF[4][4];
        #pragma unroll
        for (int nt = 0; nt < 4; nt++)
            #pragma unroll
            for (int i = 0; i < 4; i++) oF[nt][i] = 0.f;

        #pragma unroll
        for (int kk = 0; kk < 4; kk++) {
            unsigned pA[4];
            pA[0] = pack_bf16(sF[2*kk][0],   sF[2*kk][1]);
            pA[1] = pack_bf16(sF[2*kk][2],   sF[2*kk][3]);
            pA[2] = pack_bf16(sF[2*kk+1][0], sF[2*kk+1][1]);
            pA[3] = pack_bf16(sF[2*kk+1][2], sF[2*kk+1][3]);
            #pragma unroll
            for (int dh = 0; dh < 2; dh++) {
                unsigned b0, b1, b2, b3;
                int r = 16*kk + ql*8 + lrl;
                int c = 48 + 4*h + 2*dh + qh;
                LDSM4T(b0, b1, b2, b3, sb + (uint32_t)(r*1152 + SWZ16(c, r)));
                unsigned bb0[2] = {b0, b1}, bb1[2] = {b2, b3};
                mma_bf16(oF[2*dh],   pA, bb0);
                mma_bf16(oF[2*dh+1], pA, bb1);
            }
        }

        float rs0 = 1.0f / s0, rs1 = 1.0f / s1;
        #pragma unroll
        for (int nt = 0; nt < 4; nt++) {
            int col = h*32 + nt*8 + 2*tg;
            size_t t0 = (size_t)(rowbase + n0)*CH + col;
            size_t t1 = (size_t)(rowbase + n1)*CH + col;
            *(__nv_bfloat162*)&out[t0] = __floats2bfloat162_rn(oF[nt][0]*rs0, oF[nt][1]*rs0);
            *(__nv_bfloat162*)&out[t1] = __floats2bfloat162_rn(oF[nt][2]*rs1, oF[nt][3]*rs1);
        }
    }
}

// ---------------- launch ----------------
extern "C" void kernel_launch(void* const* d_in, const int* in_sizes, int n_in,
                              void* d_out, int out_size) {
    const float* x       = (const float*)d_in[0];
    const float* norm1_g = (const float*)d_in[3];
    const float* norm1_b = (const float*)d_in[4];
    const float* qkv_w   = (const float*)d_in[5];
    const float* qkv_b   = (const float*)d_in[6];
    const float* rpb     = (const float*)d_in[7];
    const float* proj_w  = (const float*)d_in[8];
    const float* proj_b  = (const float*)d_in[9];
    const float* norm2_g = (const float*)d_in[10];
    const float* norm2_b = (const float*)d_in[11];
    const float* fc1_w   = (const float*)d_in[12];
    const float* fc1_b   = (const float*)d_in[13];
    const float* fc2_w   = (const float*)d_in[14];
    const float* fc2_b   = (const float*)d_in[15];
    float* out = (float*)d_out;

    __nv_bfloat16 *qkv, *attn, *h1, *wq, *wp, *w1, *w2;
    float *x2;
    cudaGetSymbolAddress((void**)&qkv,  g_qkv);
    cudaGetSymbolAddress((void**)&attn, g_attn);
    cudaGetSymbolAddress((void**)&x2,   g_x2);
    cudaGetSymbolAddress((void**)&h1,   g_h1);
    cudaGetSymbolAddress((void**)&wq,   g_wq);
    cudaGetSymbolAddress((void**)&wp,   g_wp);
    cudaGetSymbolAddress((void**)&w1,   g_w1);
    cudaGetSymbolAddress((void**)&w2,   g_w2);

    cudaFuncSetAttribute(gemm_fk<0>, cudaFuncAttributeMaxDynamicSharedMemorySize, FK_TOT);
    cudaFuncSetAttribute(gemm_fk<1>, cudaFuncAttributeMaxDynamicSharedMemorySize, FK_TOT);
    cudaFuncSetAttribute(gemm_fk<2>, cudaFuncAttributeMaxDynamicSharedMemorySize, FK_TOT);
    cudaFuncSetAttribute(gemm_lm<3>, cudaFuncAttributeMaxDynamicSharedMemorySize, GSM);
    cudaFuncSetAttribute(attn_mma,   cudaFuncAttributeMaxDynamicSharedMemorySize, ASM_TOT);

    // 0) all weights -> bf16
    cvt_all<<<(NWQ+NWP+NW1+NW2)/1024, 256>>>(qkv_w, proj_w, fc1_w, fc2_w, wq, wp, w1, w2);
    // 1) QKV = LN1(x, gathered) @ wq^T + b   (LN1 fused into A-builder)
    gemm_fk<0><<<dim3(6, MROWS/64), 256, FK_TOT>>>(x, wq, qkv_b, norm1_g, norm1_b,
                                                   nullptr, qkv, 3*CH);
    // 2) windowed attention (tensor cores)
    attn_mma<<<BATCH*NWIN, 256, ASM_TOT>>>(qkv, rpb, attn);
    // 3) x2 = x + scatter(attn @ wp^T + b)
    gemm_fk<1><<<dim3(2, MROWS/64), 256, FK_TOT>>>(attn, wp, proj_b, nullptr, nullptr,
                                                   x, x2, CH);
    // 4) h1 = gelu(LN2(x2) @ w1^T + b)       (LN2 fused into A-builder)
    gemm_fk<2><<<dim3(8, MROWS/64), 256, FK_TOT>>>(x2, w1, fc1_b, norm2_g, norm2_b,
                                                   nullptr, h1, CHID);
    // 5) out = x2 + h1 @ w2^T + b
    gemm_lm<3><<<dim3(2, MROWS/128), 256, GSM>>>(h1, w2, fc2_b, x2, out, CHID, CH);
}

// round 17
// speedup vs baseline: 1.1687x; 1.1687x over previous
#include <cuda_runtime.h>
#include <cuda_bf16.h>
#include <math.h>
#include <stdint.h>

// ---------------- problem constants ----------------
#define BATCH 32
#define HH 64
#define WW 64
#define CH 192
#define LL (HH*WW)            // 4096
#define NHEAD 6
#define HD 32
#define WSZ 8
#define SHIFT 4
#define NTOK 64
#define NWIN 64
#define MROWS (BATCH*LL)      // 131072
#define CHID (4*CH)           // 768

// ---------------- scratch (device globals; no allocs allowed) ----------------
__device__ __nv_bfloat16 g_xn  [MROWS*CH];
__device__ __nv_bfloat16 g_qkv [MROWS*3*CH];
__device__ __nv_bfloat16 g_attn[MROWS*CH];
__device__ float         g_x2  [MROWS*CH];
__device__ __nv_bfloat16 g_xn2 [MROWS*CH];
__device__ __nv_bfloat16 g_h1  [MROWS*CHID];
// bf16 weights (converted once per launch)
__device__ __nv_bfloat16 g_wq[3*CH*CH];
__device__ __nv_bfloat16 g_wp[CH*CH];
__device__ __nv_bfloat16 g_w1[CHID*CH];
__device__ __nv_bfloat16 g_w2[CH*CHID];

// roll(-4,-4)+window-partition map (self-inverse)
__device__ __forceinline__ int win_to_img_row(int r) {
    int b   = r >> 12;
    int rem = r & 4095;
    int win = rem >> 6;
    int n   = rem & 63;
    int hs  = ((win >> 3) << 3) + (n >> 3);
    int ws  = ((win & 7)  << 3) + (n & 7);
    int hh  = (hs + SHIFT) & 63;
    int ww  = (ws + SHIFT) & 63;
    return (b << 12) + (hh << 6) + ww;
}

// ---------------- asm helpers ----------------
__device__ __forceinline__ uint32_t smem_u32(const void* p) {
    uint32_t a;
    asm("{ .reg .u64 t; cvta.to.shared.u64 t, %1; cvt.u32.u64 %0, t; }" : "=r"(a) : "l"(p));
    return a;
}
__device__ __forceinline__ void cp16(uint32_t dst, const void* src) {
    asm volatile("cp.async.cg.shared.global [%0], [%1], 16;" :: "r"(dst), "l"(src));
}
#define CP_COMMIT() asm volatile("cp.async.commit_group;" ::: "memory")
#define CP_WAIT(n)  asm volatile("cp.async.wait_group %0;" :: "n"(n) : "memory")
#define LDSM4(r0, r1, r2, r3, a) \
    asm volatile("ldmatrix.sync.aligned.m8n8.x4.shared.b16 {%0,%1,%2,%3}, [%4];" \
                 : "=r"(r0), "=r"(r1), "=r"(r2), "=r"(r3) : "r"(a))
#define LDSM4T(r0, r1, r2, r3, a) \
    asm volatile("ldmatrix.sync.aligned.m8n8.x4.trans.shared.b16 {%0,%1,%2,%3}, [%4];" \
                 : "=r"(r0), "=r"(r1), "=r"(r2), "=r"(r3) : "r"(a))

__device__ __forceinline__ void mma_bf16(float* d, const unsigned* a, const unsigned* b) {
    asm volatile(
        "mma.sync.aligned.m16n8k16.row.col.f32.bf16.bf16.f32 "
        "{%0,%1,%2,%3}, {%4,%5,%6,%7}, {%8,%9}, {%0,%1,%2,%3};"
        : "+f"(d[0]), "+f"(d[1]), "+f"(d[2]), "+f"(d[3])
        : "r"(a[0]), "r"(a[1]), "r"(a[2]), "r"(a[3]), "r"(b[0]), "r"(b[1]));
}
__device__ __forceinline__ unsigned pack_bf16(float lo, float hi) {
    __nv_bfloat162 h = __floats2bfloat162_rn(lo, hi);
    return *(unsigned*)&h;
}
#define SWZ16(c, r) ((((c) & ~7) | (((c) & 7) ^ ((r) & 7))) << 4)

// ---------------- fused fp32 -> bf16 weight conversion ----------------
#define NWQ (3*CH*CH)
#define NWP (CH*CH)
#define NW1 (CHID*CH)
#define NW2 (CH*CHID)
__global__ void cvt_all(const float* __restrict__ wq, const float* __restrict__ wp,
                        const float* __restrict__ w1, const float* __restrict__ w2,
                        __nv_bfloat16* __restrict__ dq, __nv_bfloat16* __restrict__ dp,
                        __nv_bfloat16* __restrict__ d1, __nv_bfloat16* __restrict__ d2) {
    int i = (blockIdx.x * 256 + threadIdx.x) * 4;
    const float* s; __nv_bfloat16* d; int off;
    if (i < NWQ)                       { s = wq; d = dq; off = i; }
    else if (i < NWQ+NWP)              { s = wp; d = dp; off = i - NWQ; }
    else if (i < NWQ+NWP+NW1)          { s = w1; d = d1; off = i - NWQ - NWP; }
    else if (i < NWQ+NWP+NW1+NW2)      { s = w2; d = d2; off = i - NWQ - NWP - NW1; }
    else return;
    float4 v = *(const float4*)&s[off];
    *(__nv_bfloat162*)&d[off]   = __floats2bfloat162_rn(v.x, v.y);
    *(__nv_bfloat162*)&d[off+2] = __floats2bfloat162_rn(v.z, v.w);
}

// ---------------- LayerNorm: one warp per row ----------------
__global__ __launch_bounds__(256)
void ln_kernel(const float* __restrict__ x, const float* __restrict__ g,
               const float* __restrict__ b, __nv_bfloat16* __restrict__ out) {
    int w = threadIdx.x >> 5, lane = threadIdx.x & 31;
    int row = blockIdx.x * 8 + w;
    const float* xr = x + (size_t)row * CH;
    float v[6];
    float s = 0.f, s2 = 0.f;
    #pragma unroll
    for (int i = 0; i < 6; i++) {
        v[i] = xr[lane + 32*i];
        s  += v[i];
        s2 += v[i]*v[i];
    }
    #pragma unroll
    for (int o = 16; o > 0; o >>= 1) {
        s  += __shfl_xor_sync(0xffffffffu, s,  o);
        s2 += __shfl_xor_sync(0xffffffffu, s2, o);
    }
    float mean = s * (1.0f/CH);
    float var  = s2 * (1.0f/CH) - mean*mean;
    float inv  = rsqrtf(var + 1e-5f);
    __nv_bfloat16* orow = out + (size_t)row * CH;
    #pragma unroll
    for (int i = 0; i < 6; i++) {
        int c = lane + 32*i;
        orow[c] = __float2bfloat16((v[i] - mean) * inv * g[c] + b[c]);
    }
}

// ---------------- fragment loader (shared by gemm mainloop) ----------------
__device__ __forceinline__ void frag_load(unsigned (&aF)[2][4], unsigned (&bF)[6][2],
                                          uint32_t aB, uint32_t bB, int ck,
                                          int qh, int ql,
                                          const int (&aRow)[2], const int (&bRow)[3]) {
    #pragma unroll
    for (int mt = 0; mt < 2; mt++) {
        int ch = ck + qh;
        uint32_t ad = aB + (uint32_t)(aRow[mt]*128 + (((ch ^ (aRow[mt] & 7)) << 4)));
        LDSM4(aF[mt][0], aF[mt][1], aF[mt][2], aF[mt][3], ad);
    }
    #pragma unroll
    for (int p = 0; p < 3; p++) {
        int ch = ck + ql;
        uint32_t bd = bB + (uint32_t)(bRow[p]*128 + (((ch ^ (bRow[p] & 7)) << 4)));
        LDSM4(bF[2*p][0], bF[2*p][1], bF[2*p+1][0], bF[2*p+1][1], bd);
    }
}

// ---------------- bf16 mma GEMM: 3-stage cp.async + fragment double-buffer ----------------
// 256 threads = 8 warps (4m x 2n), BM=128, BN=96, BK=64, warp tile 32x48.
#define STG   28672
#define BOFF  16384
#define GSM   (3*STG + 512)

template<int MODE>
__global__ __launch_bounds__(256, 2)
void gemm_lm(const __nv_bfloat16* __restrict__ A, const __nv_bfloat16* __restrict__ Bw,
             const float* __restrict__ bias, const float* __restrict__ resid,
             void* __restrict__ CoutV, int K, int Ncols) {
    extern __shared__ __align__(1024) unsigned char smem[];
    uint32_t sb = smem_u32(smem);
    int* rowIdx = (int*)(smem + 3*STG);

    int tid = threadIdx.x;
    int rowBase = blockIdx.y * 128;
    int colBase = blockIdx.x * 96;

    if (tid < 128) {
        int r = rowBase + tid;
        rowIdx[tid] = (MODE == 0) ? win_to_img_row(r) : r;
    }
    __syncthreads();

    int lc = tid & 7;
    int lr0 = tid >> 3;
    const char* aPtr[4]; uint32_t aDst[4];
    #pragma unroll
    for (int i = 0; i < 4; i++) {
        int r = lr0 + 32*i;
        aPtr[i] = (const char*)(A + (size_t)rowIdx[r]*K + 8*lc);
        aDst[i] = (uint32_t)(r*128 + ((lc ^ (r & 7)) << 4));
    }
    const char* bPtr[3]; uint32_t bDst[3];
    #pragma unroll
    for (int i = 0; i < 3; i++) {
        int r = lr0 + 32*i;
        bPtr[i] = (const char*)(Bw + (size_t)(colBase + r)*K + 8*lc);
        bDst[i] = (uint32_t)(r*128 + ((lc ^ (r & 7)) << 4));
    }

    const int T = K >> 6;

    // prologue: stages 0,1
    {
        #pragma unroll
        for (int i = 0; i < 4; i++) cp16(sb + aDst[i], aPtr[i]);
        #pragma unroll
        for (int i = 0; i < 3; i++) cp16(sb + BOFF + bDst[i], bPtr[i]);
        CP_COMMIT();
        #pragma unroll
        for (int i = 0; i < 4; i++) cp16(sb + STG + aDst[i], aPtr[i] + 128);
        #pragma unroll
        for (int i = 0; i < 3; i++) cp16(sb + STG + BOFF + bDst[i], bPtr[i] + 128);
        CP_COMMIT();
    }

    int w = tid >> 5, lane = tid & 31;
    int wm = w >> 1, wn = w & 1;
    int mW = wm * 32, nW = wn * 48;
    int q  = lane >> 3, lrl = lane & 7;
    int qh = q >> 1, ql = q & 1;

    int aRow[2];
    #pragma unroll
    for (int mt = 0; mt < 2; mt++) aRow[mt] = mW + 16*mt + ql*8 + lrl;
    int bRow[3];
    #pragma unroll
    for (int p = 0; p < 3; p++) bRow[p] = nW + 8*(2*p + qh) + lrl;

    float acc[2][6][4];
    #pragma unroll
    for (int mt = 0; mt < 2; mt++)
        #pragma unroll
        for (int nt = 0; nt < 6; nt++)
            #pragma unroll
            for (int i = 0; i < 4; i++) acc[mt][nt][i] = 0.f;

    unsigned aFb[2][2][4], bFb[2][6][2];

    int cBuf = 0, wBuf = 2;
    for (int t = 0; t < T; t++) {
        if (t + 1 < T) { CP_WAIT(1); } else { CP_WAIT(0); }
        __syncthreads();

        if (t + 2 < T) {
            int k0 = (t + 2) << 7;            // bytes: 64 bf16 = 128B
            uint32_t dB = sb + (uint32_t)wBuf * STG;
            #pragma unroll
            for (int i = 0; i < 4; i++) cp16(dB + aDst[i], aPtr[i] + k0);
            #pragma unroll
            for (int i = 0; i < 3; i++) cp16(dB + BOFF + bDst[i], bPtr[i] + k0);
            CP_COMMIT();
        }

        uint32_t aB = sb + (uint32_t)cBuf * STG;
        uint32_t bB = aB + BOFF;

        // fragment double-buffer: prefetch kk+1 before consuming kk
        frag_load(aFb[0], bFb[0], aB, bB, 0, qh, ql, aRow, bRow);
        #pragma unroll
        for (int kk = 0; kk < 4; kk++) {
            if (kk < 3)
                frag_load(aFb[(kk+1)&1], bFb[(kk+1)&1], aB, bB, (kk+1)*2, qh, ql, aRow, bRow);
            int fb = kk & 1;
            #pragma unroll
            for (int mt = 0; mt < 2; mt++)
                #pragma unroll
                for (int nt = 0; nt < 6; nt++)
                    mma_bf16(acc[mt][nt], aFb[fb][mt], bFb[fb][nt]);
        }

        cBuf = (cBuf == 2) ? 0 : cBuf + 1;
        wBuf = (wBuf == 2) ? 0 : wBuf + 1;
    }

    int g  = lane >> 2, tg = lane & 3;
    float*         CoutF = (float*)CoutV;
    __nv_bfloat16* CoutB = (__nv_bfloat16*)CoutV;
    #pragma unroll
    for (int mt = 0; mt < 2; mt++) {
        #pragma unroll
        for (int half = 0; half < 2; half++) {
            int row = rowBase + mW + 16*mt + g + half*8;
            int dst = (MODE == 1) ? win_to_img_row(row) : row;
            #pragma unroll
            for (int nt = 0; nt < 6; nt++) {
                int col = colBase + nW + 8*nt + 2*tg;
                float2 bb = *(const float2*)&bias[col];
                float v0 = acc[mt][nt][half*2 + 0] + bb.x;
                float v1 = acc[mt][nt][half*2 + 1] + bb.y;
                if (MODE == 1 || MODE == 3) {
                    float2 rr = *(const float2*)&resid[(size_t)dst*Ncols + col];
                    float2 o; o.x = rr.x + v0; o.y = rr.y + v1;
                    *(float2*)&CoutF[(size_t)dst*Ncols + col] = o;
                } else if (MODE == 2) {
                    float o0 = 0.5f * v0 * (1.0f + erff(v0 * 0.70710678118654752f));
                    float o1 = 0.5f * v1 * (1.0f + erff(v1 * 0.70710678118654752f));
                    *(__nv_bfloat162*)&CoutB[(size_t)dst*Ncols + col] = __floats2bfloat162_rn(o0, o1);
                } else {
                    *(__nv_bfloat162*)&CoutB[(size_t)dst*Ncols + col] = __floats2bfloat162_rn(v0, v1);
                }
            }
        }
    }
}

// ---------------- tensor-core attention (R12 winner, unchanged) ----------------
__device__ __forceinline__ int region_of(int p) {
    return (p < 56) ? 0 : ((p < 60) ? 1 : 2);
}
#define ASM_RPB  73728
#define ASM_REG  (73728 + 5400)
#define ASM_TOT  (73728 + 5400 + 256)

__global__ __launch_bounds__(256)
void attn_mma(const __nv_bfloat16* __restrict__ qkv, const float* __restrict__ rpb,
              __nv_bfloat16* __restrict__ out) {
    extern __shared__ __align__(1024) unsigned char sm[];
    uint32_t sb = smem_u32(sm);
    float* rpbs = (float*)(sm + ASM_RPB);
    int*   regl = (int*)(sm + ASM_REG);

    int tid = threadIdx.x;
    int win = blockIdx.x;
    int rowbase = win * 64;

    #pragma unroll
    for (int i = 0; i < 18; i++) {
        int id = tid + i*256;
        int r = id / 72, c = id % 72;
        uint32_t dst = sb + (uint32_t)(r*1152 + SWZ16(c, r));
        cp16(dst, qkv + (size_t)(rowbase + r)*576 + c*8);
    }
    CP_COMMIT();
    for (int i = tid; i < 225*NHEAD; i += 256) {
        int idx = i / NHEAD, h = i % NHEAD;
        rpbs[h*225 + idx] = rpb[i];
    }
    if (tid < 64) {
        int wr = (win & 63) >> 3, wc = win & 7;
        regl[tid] = region_of(wr*8 + (tid >> 3))*3 + region_of(wc*8 + (tid & 7));
    }
    CP_WAIT(0);
    __syncthreads();

    int w = tid >> 5, lane = tid & 31;
    int q  = lane >> 3, lrl = lane & 7;
    int qh = q >> 1,   ql  = q & 1;
    int g  = lane >> 2, tg = lane & 3;

    for (int task = w; task < 24; task += 8) {
        int h = task >> 2, mt = task & 3;

        float sF[8][4];
        #pragma unroll
        for (int nt = 0; nt < 8; nt++)
            #pragma unroll
            for (int i = 0; i < 4; i++) sF[nt][i] = 0.f;

        #pragma unroll
        for (int kk = 0; kk < 2; kk++) {
            unsigned aF[4];
            {
                int r = mt*16 + ql*8 + lrl;
                int c = 4*h + 2*kk + qh;
                LDSM4(aF[0], aF[1], aF[2], aF[3], sb + (uint32_t)(r*1152 + SWZ16(c, r)));
            }
            #pragma unroll
            for (int p = 0; p < 4; p++) {
                unsigned b0, b1, b2, b3;
                int r = 16*p + qh*8 + lrl;
                int c = 24 + 4*h + 2*kk + ql;
                LDSM4(b0, b1, b2, b3, sb + (uint32_t)(r*1152 + SWZ16(c, r)));
                unsigned bb0[2] = {b0, b1}, bb1[2] = {b2, b3};
                mma_bf16(sF[2*p],   aF, bb0);
                mma_bf16(sF[2*p+1], aF, bb1);
            }
        }

        int n0 = mt*16 + g, n1 = n0 + 8;
        int r0g = regl[n0], r1g = regl[n1];
        int in0 = n0 >> 3, jn0 = n0 & 7;
        int in1 = n1 >> 3, jn1 = n1 & 7;
        const float* rh = rpbs + h*225;
        int jb0 = jn0 + 7 - 2*tg;
        int jb1 = jn1 + 7 - 2*tg;
        const float scale = 0.17677669529663687f;
        float mx0 = -1e30f, mx1 = -1e30f;
        #pragma unroll
        for (int nt = 0; nt < 8; nt++) {
            const float* r0p = rh + (in0 - nt + 7)*15 + jb0;
            const float* r1p = rh + (in1 - nt + 7)*15 + jb1;
            #pragma unroll
            for (int e = 0; e < 2; e++) {
                int col = nt*8 + 2*tg + e;
                int rm = regl[col];
                float v0 = sF[nt][e]   * scale + r0p[-e] + ((r0g == rm) ? 0.f : -100.f);
                float v1 = sF[nt][2+e] * scale + r1p[-e] + ((r1g == rm) ? 0.f : -100.f);
                sF[nt][e] = v0; sF[nt][2+e] = v1;
                mx0 = fmaxf(mx0, v0); mx1 = fmaxf(mx1, v1);
            }
        }
        mx0 = fmaxf(mx0, __shfl_xor_sync(0xffffffffu, mx0, 1));
        mx0 = fmaxf(mx0, __shfl_xor_sync(0xffffffffu, mx0, 2));
        mx1 = fmaxf(mx1, __shfl_xor_sync(0xffffffffu, mx1, 1));
        mx1 = fmaxf(mx1, __shfl_xor_sync(0xffffffffu, mx1, 2));
        float s0 = 0.f, s1 = 0.f;
        #pragma unroll
        for (int nt = 0; nt < 8; nt++) {
            #pragma unroll
            for (int e = 0; e < 2; e++) {
                float e0 = __expf(sF[nt][e]   - mx0);
                float e1 = __expf(sF[nt][2+e] - mx1);
                sF[nt][e] = e0;   s0 += e0;
                sF[nt][2+e] = e1; s1 += e1;
            }
        }
        s0 += __shfl_xor_sync(0xffffffffu, s0, 1);
        s0 += __shfl_xor_sync(0xffffffffu, s0, 2);
        s1 += __shfl_xor_sync(0xffffffffu, s1, 1);
        s1 += __shfl_xor_sync(0xffffffffu, s1, 2);

        float oF[4][4];
        #pragma unroll
        for (int nt = 0; nt < 4; nt++)
            #pragma unroll
            for (int i = 0; i < 4; i++) oF[nt][i] = 0.f;

        #pragma unroll
        for (int kk = 0; kk < 4; kk++) {
            unsigned pA[4];
            pA[0] = pack_bf16(sF[2*kk][0],   sF[2*kk][1]);
            pA[1] = pack_bf16(sF[2*kk][2],   sF[2*kk][3]);
            pA[2] = pack_bf16(sF[2*kk+1][0], sF[2*kk+1][1]);
            pA[3] = pack_bf16(sF[2*kk+1][2], sF[2*kk+1][3]);
            #pragma unroll
            for (int dh = 0; dh < 2; dh++) {
                unsigned b0, b1, b2, b3;
                int r = 16*kk + ql*8 + lrl;
                int c = 48 + 4*h + 2*dh + qh;
                LDSM4T(b0, b1, b2, b3, sb + (uint32_t)(r*1152 + SWZ16(c, r)));
                unsigned bb0[2] = {b0, b1}, bb1[2] = {b2, b3};
                mma_bf16(oF[2*dh],   pA, bb0);
                mma_bf16(oF[2*dh+1], pA, bb1);
            }
        }

        float rs0 = 1.0f / s0, rs1 = 1.0f / s1;
        #pragma unroll
        for (int nt = 0; nt < 4; nt++) {
            int col = h*32 + nt*8 + 2*tg;
            size_t t0 = (size_t)(rowbase + n0)*CH + col;
            size_t t1 = (size_t)(rowbase + n1)*CH + col;
            *(__nv_bfloat162*)&out[t0] = __floats2bfloat162_rn(oF[nt][0]*rs0, oF[nt][1]*rs0);
            *(__nv_bfloat162*)&out[t1] = __floats2bfloat162_rn(oF[nt][2]*rs1, oF[nt][3]*rs1);
        }
    }
}

// ---------------- launch ----------------
extern "C" void kernel_launch(void* const* d_in, const int* in_sizes, int n_in,
                              void* d_out, int out_size) {
    const float* x       = (const float*)d_in[0];
    const float* norm1_g = (const float*)d_in[3];
    const float* norm1_b = (const float*)d_in[4];
    const float* qkv_w   = (const float*)d_in[5];
    const float* qkv_b   = (const float*)d_in[6];
    const float* rpb     = (const float*)d_in[7];
    const float* proj_w  = (const float*)d_in[8];
    const float* proj_b  = (const float*)d_in[9];
    const float* norm2_g = (const float*)d_in[10];
    const float* norm2_b = (const float*)d_in[11];
    const float* fc1_w   = (const float*)d_in[12];
    const float* fc1_b   = (const float*)d_in[13];
    const float* fc2_w   = (const float*)d_in[14];
    const float* fc2_b   = (const float*)d_in[15];
    float* out = (float*)d_out;

    __nv_bfloat16 *xn, *qkv, *attn, *xn2, *h1, *wq, *wp, *w1, *w2;
    float *x2;
    cudaGetSymbolAddress((void**)&xn,   g_xn);
    cudaGetSymbolAddress((void**)&qkv,  g_qkv);
    cudaGetSymbolAddress((void**)&attn, g_attn);
    cudaGetSymbolAddress((void**)&x2,   g_x2);
    cudaGetSymbolAddress((void**)&xn2,  g_xn2);
    cudaGetSymbolAddress((void**)&h1,   g_h1);
    cudaGetSymbolAddress((void**)&wq,   g_wq);
    cudaGetSymbolAddress((void**)&wp,   g_wp);
    cudaGetSymbolAddress((void**)&w1,   g_w1);
    cudaGetSymbolAddress((void**)&w2,   g_w2);

    cudaFuncSetAttribute(gemm_lm<0>, cudaFuncAttributeMaxDynamicSharedMemorySize, GSM);
    cudaFuncSetAttribute(gemm_lm<1>, cudaFuncAttributeMaxDynamicSharedMemorySize, GSM);
    cudaFuncSetAttribute(gemm_lm<2>, cudaFuncAttributeMaxDynamicSharedMemorySize, GSM);
    cudaFuncSetAttribute(gemm_lm<3>, cudaFuncAttributeMaxDynamicSharedMemorySize, GSM);
    cudaFuncSetAttribute(attn_mma,   cudaFuncAttributeMaxDynamicSharedMemorySize, ASM_TOT);

    // 0) all weights -> bf16
    cvt_all<<<(NWQ+NWP+NW1+NW2)/1024, 256>>>(qkv_w, proj_w, fc1_w, fc2_w, wq, wp, w1, w2);
    // 1) LN1
    ln_kernel<<<MROWS/8, 256>>>(x, norm1_g, norm1_b, xn);
    // 2) QKV (gathered A: shift + window partition fused)
    gemm_lm<0><<<dim3(6, MROWS/128), 256, GSM>>>(xn, wq, qkv_b, nullptr, qkv, CH, 3*CH);
    // 3) windowed attention (tensor cores)
    attn_mma<<<BATCH*NWIN, 256, ASM_TOT>>>(qkv, rpb, attn);
    // 4) proj + window reverse + roll + residual
    gemm_lm<1><<<dim3(2, MROWS/128), 256, GSM>>>(attn, wp, proj_b, x, x2, CH, CH);
    // 5) LN2
    ln_kernel<<<MROWS/8, 256>>>(x2, norm2_g, norm2_b, xn2);
    // 6) fc1 + GELU
    gemm_lm<2><<<dim3(8, MROWS/128), 256, GSM>>>(xn2, w1, fc1_b, nullptr, h1, CH, CHID);
    // 7) fc2 + residual -> out
    gemm_lm<3><<<dim3(2, MROWS/128), 256, GSM>>>(h1, w2, fc2_b, x2, out, CHID, CH);
}